// round 8
// baseline (speedup 1.0000x reference)
#include <cuda_runtime.h>
#include <cuda_fp16.h>
#include <math.h>
#include <stdint.h>

#define N 8192
#define D 256
#define K3 256                 // fp16-quantized embedding, exact dist on quantized vecs
#define TM 128
#define TN 128
#define NTB (N / TM)           // 64
#define NTILES (NTB * (NTB + 1) / 2)   // 2080
#define KC 64                  // k-elems per chunk = 128B rows
#define NC (K3 / KC)           // 4
#define MARGIN 0.3f
#define POS_INF_BITS 0x7f800000

// 3-stage smem: stage = A(16KB) + B(16KB)
#define STAGE_BYTES 32768
#define OFF_STAT (3 * STAGE_BYTES)     // 98304
#define STAT_BYTES 4096
#define SMEM_BYTES (OFF_STAT + STAT_BYTES + 1024)

// -------- device scratch --------
__device__ __half g_F[(size_t)N * K3];   // fp16-quantized normalized features
__device__ float g_sq[N];                // exact ||f_hat||^2 in fp32
__device__ int   g_lab[N];
__device__ int   g_maxpos[N];   // float bits (dist >= 0 -> monotone as int)
__device__ int   g_minneg[N];
__device__ int   g_done;

// -------- helpers --------
__device__ __forceinline__ uint32_t smem_u32(const void* p) {
    return (uint32_t)__cvta_generic_to_shared(p);
}
__device__ __forceinline__ uint32_t swz(int row, int g) {   // 128B rows, 16B groups
    return (uint32_t)(row * 128 + ((g ^ (row & 7)) << 4));
}
__device__ __forceinline__ void cp16(uint32_t saddr, const void* gaddr) {
    asm volatile("cp.async.cg.shared.global [%0], [%1], 16;"
                 :: "r"(saddr), "l"(gaddr) : "memory");
}
__device__ __forceinline__ void ldsm4(uint32_t& r0, uint32_t& r1, uint32_t& r2,
                                      uint32_t& r3, uint32_t addr) {
    asm volatile("ldmatrix.sync.aligned.m8n8.x4.shared.b16 {%0,%1,%2,%3}, [%4];"
                 : "=r"(r0), "=r"(r1), "=r"(r2), "=r"(r3) : "r"(addr));
}
__device__ __forceinline__ void mma16816(float* d, const uint32_t* a, const uint32_t* b) {
    asm volatile(
        "mma.sync.aligned.m16n8k16.row.col.f32.f16.f16.f32 "
        "{%0,%1,%2,%3}, {%4,%5,%6,%7}, {%8,%9}, {%0,%1,%2,%3};"
        : "+f"(d[0]), "+f"(d[1]), "+f"(d[2]), "+f"(d[3])
        : "r"(a[0]), "r"(a[1]), "r"(a[2]), "r"(a[3]), "r"(b[0]), "r"(b[1]));
}

// -------- 1) label detect/convert + stats init + counter reset --------
__global__ void labels_kernel(const void* __restrict__ labels_raw) {
    const int* w = (const int*)labels_raw;
    __shared__ int any_odd_nonzero;
    if (threadIdx.x == 0) { any_odd_nonzero = 0; g_done = 0; }
    __syncthreads();
    int local = 0;
    for (int i = threadIdx.x; i < N; i += blockDim.x)
        if (w[2 * i + 1] != 0) local = 1;
    if (local) atomicOr(&any_odd_nonzero, 1);
    __syncthreads();
    bool is64 = (any_odd_nonzero == 0);
    for (int i = threadIdx.x; i < N; i += blockDim.x) {
        g_lab[i] = is64 ? w[2 * i] : w[i];
        g_maxpos[i] = 0;
        g_minneg[i] = POS_INF_BITS;
    }
}

// -------- 2) normalize, quantize to fp16, exact sq of quantized --------
__global__ void normalize_convert_kernel(const float* __restrict__ f) {
    int row = blockIdx.x;
    int tid = threadIdx.x;           // 256 = D
    float v = f[row * D + tid];
    float ss = v * v;
    #pragma unroll
    for (int o = 16; o > 0; o >>= 1) ss += __shfl_xor_sync(0xffffffffu, ss, o);
    __shared__ float warp_s[8];
    int wid = tid >> 5, lid = tid & 31;
    if (lid == 0) warp_s[wid] = ss;
    __syncthreads();
    if (wid == 0) {
        float s = (lid < 8) ? warp_s[lid] : 0.0f;
        #pragma unroll
        for (int o = 4; o > 0; o >>= 1) s += __shfl_xor_sync(0xffffffffu, s, o);
        if (lid == 0) warp_s[0] = s;
    }
    __syncthreads();
    float inv = 1.0f / fmaxf(sqrtf(warp_s[0]), 1e-12f);
    __half hq = __float2half_rn(v * inv);
    g_F[(size_t)row * K3 + tid] = hq;
    // second reduction: exact squared norm of the QUANTIZED vector
    float h = __half2float(hq);
    float s2 = h * h;
    #pragma unroll
    for (int o = 16; o > 0; o >>= 1) s2 += __shfl_xor_sync(0xffffffffu, s2, o);
    __syncthreads();
    if (lid == 0) warp_s[wid] = s2;
    __syncthreads();
    if (wid == 0) {
        float s = (lid < 8) ? warp_s[lid] : 0.0f;
        #pragma unroll
        for (int o = 4; o > 0; o >>= 1) s += __shfl_xor_sync(0xffffffffu, s, o);
        if (lid == 0) g_sq[row] = s;
    }
}

// -------- cp.async issue of one k-chunk into one smem stage --------
__device__ __forceinline__ void issue_chunk(uint32_t sb, int gi0, int gj0,
                                            int c, int tid) {
    uint32_t stage = sb + (uint32_t)(c % 3) * STAGE_BYTES;
    #pragma unroll
    for (int l = 0; l < 4; l++) {
        int idx = tid + l * 256;
        int row = idx >> 3, g = idx & 7;
        cp16(stage + swz(row, g),
             g_F + (size_t)(gi0 + row) * K3 + c * KC + g * 8);
        cp16(stage + 16384u + swz(row, g),
             g_F + (size_t)(gj0 + row) * K3 + c * KC + g * 8);
    }
}

// -------- 3) HMMA gram + fused epilogue + fused loss, triangular grid --------
__global__ void __launch_bounds__(256, 2) tile_kernel(float* __restrict__ out) {
    // linear index -> (bi, bj) with bj >= bi
    int t = blockIdx.x;
    int p = (int)((sqrtf(8.0f * (float)t + 1.0f) - 1.0f) * 0.5f);
    while ((p + 1) * (p + 2) / 2 <= t) p++;
    while (p * (p + 1) / 2 > t) p--;
    int bi = t - p * (p + 1) / 2;
    int bj = p;

    extern __shared__ __align__(128) char dsm[];
    uint32_t raw = smem_u32(dsm);
    uint32_t sb = (raw + 1023) & ~1023u;
    char* base = dsm + (sb - raw);

    int*   lab_i_s = (int*)(base + OFF_STAT);
    float* sq_i_s  = (float*)(base + OFF_STAT + 512);
    int*   lab_j_s = (int*)(base + OFF_STAT + 1024);
    float* sq_j_s  = (float*)(base + OFF_STAT + 1536);
    int*   smax_i  = (int*)(base + OFF_STAT + 2048);
    int*   smin_i  = (int*)(base + OFF_STAT + 2560);
    int*   smax_j  = (int*)(base + OFF_STAT + 3072);
    int*   smin_j  = (int*)(base + OFF_STAT + 3584);

    int tid = threadIdx.x;
    int wid = tid >> 5, lane = tid & 31;
    int wr = wid & 3, wc = wid >> 2;          // 4x2 warp grid: 32 rows x 64 cols
    int gi0 = bi * TM, gj0 = bj * TN;

    // prologue: chunks 0 and 1 into stages 0,1
    issue_chunk(sb, gi0, gj0, 0, tid);
    asm volatile("cp.async.commit_group;" ::: "memory");
    issue_chunk(sb, gi0, gj0, 1, tid);
    asm volatile("cp.async.commit_group;" ::: "memory");

    if (tid < 128) {
        lab_i_s[tid] = g_lab[gi0 + tid];
        sq_i_s[tid]  = g_sq[gi0 + tid];
        lab_j_s[tid] = g_lab[gj0 + tid];
        sq_j_s[tid]  = g_sq[gj0 + tid];
        smax_i[tid] = 0; smin_i[tid] = POS_INF_BITS;
        smax_j[tid] = 0; smin_j[tid] = POS_INF_BITS;
    }

    float d[16][4];
    #pragma unroll
    for (int q = 0; q < 16; q++)
        #pragma unroll
        for (int r = 0; r < 4; r++) d[q][r] = 0.0f;

    // ldmatrix lane addressing
    int a_row = wr * 32 + ((lane >> 3) & 1) * 8 + (lane & 7);   // + mt*16
    int a_gh  = lane >> 4;
    int b_row = wc * 64 + ((lane >> 4) & 1) * 8 + (lane & 7);   // + p*16
    int b_gh  = (lane >> 3) & 1;

    uint32_t afr[2][8];     // A double-buffered across kk
    uint32_t bfr[2][4];     // B rolling buffer, one ldsm4 (16 cols) ahead

    for (int c = 0; c < NC; c++) {
        asm volatile("cp.async.wait_group 1;" ::: "memory");
        __syncthreads();
        if (c + 2 < NC) issue_chunk(sb, gi0, gj0, c + 2, tid);
        asm volatile("cp.async.commit_group;" ::: "memory");

        uint32_t abase = sb + (uint32_t)(c % 3) * STAGE_BYTES;
        uint32_t bbase = abase + 16384u;

        // preload kk=0: A fragments + first B ldsm
        ldsm4(afr[0][0], afr[0][1], afr[0][2], afr[0][3], abase + swz(a_row,      a_gh));
        ldsm4(afr[0][4], afr[0][5], afr[0][6], afr[0][7], abase + swz(a_row + 16, a_gh));
        ldsm4(bfr[0][0], bfr[0][1], bfr[0][2], bfr[0][3], bbase + swz(b_row, b_gh));

        #pragma unroll
        for (int kk = 0; kk < 4; kk++) {
            int acur = kk & 1, anxt = acur ^ 1;
            if (kk < 3) {   // prefetch next kk's A fragments
                ldsm4(afr[anxt][0], afr[anxt][1], afr[anxt][2], afr[anxt][3],
                      abase + swz(a_row,      (kk + 1) * 2 + a_gh));
                ldsm4(afr[anxt][4], afr[anxt][5], afr[anxt][6], afr[anxt][7],
                      abase + swz(a_row + 16, (kk + 1) * 2 + a_gh));
            }
            #pragma unroll
            for (int pp = 0; pp < 4; pp++) {
                int bcur = pp & 1, bnxt = bcur ^ 1;
                // prefetch next B ldsm (next pp, or pp=0 of next kk)
                if (pp < 3)
                    ldsm4(bfr[bnxt][0], bfr[bnxt][1], bfr[bnxt][2], bfr[bnxt][3],
                          bbase + swz(b_row + (pp + 1) * 16, kk * 2 + b_gh));
                else if (kk < 3)
                    ldsm4(bfr[bnxt][0], bfr[bnxt][1], bfr[bnxt][2], bfr[bnxt][3],
                          bbase + swz(b_row, (kk + 1) * 2 + b_gh));
                // 4 MMAs consuming bfr[bcur] (cols nt=2pp, 2pp+1)
                mma16816(d[2 * pp],     &afr[acur][0], &bfr[bcur][0]);
                mma16816(d[2 * pp + 1], &afr[acur][0], &bfr[bcur][2]);
                mma16816(d[8 + 2 * pp],     &afr[acur][4], &bfr[bcur][0]);
                mma16816(d[8 + 2 * pp + 1], &afr[acur][4], &bfr[bcur][2]);
            }
        }
    }

    // ---- epilogue: dist + masked max/min ----
    float rmx[4], rmn[4], si[4];
    int li[4];
    #pragma unroll
    for (int mt = 0; mt < 2; mt++)
        #pragma unroll
        for (int h = 0; h < 2; h++) {
            int row = wr * 32 + mt * 16 + h * 8 + (lane >> 2);
            li[mt * 2 + h] = lab_i_s[row];
            si[mt * 2 + h] = sq_i_s[row];
            rmx[mt * 2 + h] = 0.0f;
            rmn[mt * 2 + h] = __int_as_float(POS_INF_BITS);
        }

    #pragma unroll
    for (int nt = 0; nt < 8; nt++) {
        #pragma unroll
        for (int cc = 0; cc < 2; cc++) {
            int col = wc * 64 + nt * 8 + (lane & 3) * 2 + cc;
            int lj = lab_j_s[col];
            float sj = sq_j_s[col];
            float pmax = 0.0f, nmin = __int_as_float(POS_INF_BITS);
            #pragma unroll
            for (int mt = 0; mt < 2; mt++)
                #pragma unroll
                for (int h = 0; h < 2; h++) {
                    float g = d[mt * 8 + nt][h * 2 + cc];
                    float d2 = si[mt * 2 + h] + sj - 2.0f * g;
                    float dist = sqrtf(fmaxf(d2, 1e-12f));
                    if (li[mt * 2 + h] == lj) {
                        rmx[mt * 2 + h] = fmaxf(rmx[mt * 2 + h], dist);
                        pmax = fmaxf(pmax, dist);
                    } else {
                        rmn[mt * 2 + h] = fminf(rmn[mt * 2 + h], dist);
                        nmin = fminf(nmin, dist);
                    }
                }
            unsigned pm = __float_as_uint(pmax), nm = __float_as_uint(nmin);
            #pragma unroll
            for (int o = 4; o <= 16; o <<= 1) {
                unsigned pp = __shfl_xor_sync(0xffffffffu, pm, o);
                unsigned nn = __shfl_xor_sync(0xffffffffu, nm, o);
                pm = pm > pp ? pm : pp;
                nm = nm < nn ? nm : nn;
            }
            if ((lane >> 2) == 0) {
                atomicMax(&smax_j[col], (int)pm);
                atomicMin(&smin_j[col], (int)nm);
            }
        }
    }
    #pragma unroll
    for (int r4 = 0; r4 < 4; r4++) {
        unsigned pm = __float_as_uint(rmx[r4]), nm = __float_as_uint(rmn[r4]);
        #pragma unroll
        for (int o = 1; o <= 2; o <<= 1) {
            unsigned pp = __shfl_xor_sync(0xffffffffu, pm, o);
            unsigned nn = __shfl_xor_sync(0xffffffffu, nm, o);
            pm = pm > pp ? pm : pp;
            nm = nm < nn ? nm : nn;
        }
        if ((lane & 3) == 0) {
            int row = wr * 32 + (r4 >> 1) * 16 + (r4 & 1) * 8 + (lane >> 2);
            atomicMax(&smax_i[row], (int)pm);
            atomicMin(&smin_i[row], (int)nm);
        }
    }
    __syncthreads();
    if (tid < 128) {
        atomicMax(&g_maxpos[gi0 + tid], smax_i[tid]);
        atomicMin(&g_minneg[gi0 + tid], smin_i[tid]);
        atomicMax(&g_maxpos[gj0 + tid], smax_j[tid]);
        atomicMin(&g_minneg[gj0 + tid], smin_j[tid]);
    }

    // ---- fused loss: last CTA to finish reduces the mean ----
    __shared__ int s_last;
    __threadfence();
    __syncthreads();
    if (tid == 0) {
        int v = atomicAdd(&g_done, 1);
        s_last = (v == NTILES - 1) ? 1 : 0;
    }
    __syncthreads();
    if (s_last) {
        __threadfence();
        float s = 0.0f;
        #pragma unroll
        for (int k = 0; k < N / 256; k++) {       // fixed order -> deterministic
            int i = k * 256 + tid;
            float mp = __int_as_float(g_maxpos[i]);
            float mn = __int_as_float(g_minneg[i]);
            float l = mp - mn + MARGIN;
            s += (l > 0.0f) ? l : 0.0f;
        }
        #pragma unroll
        for (int o = 16; o > 0; o >>= 1) s += __shfl_xor_sync(0xffffffffu, s, o);
        float* wsum = (float*)(base + OFF_STAT);  // stats no longer needed
        if (lane == 0) wsum[wid] = s;
        __syncthreads();
        if (wid == 0) {
            float tt = (lane < 8) ? wsum[lane] : 0.0f;
            #pragma unroll
            for (int o = 4; o > 0; o >>= 1) tt += __shfl_xor_sync(0xffffffffu, tt, o);
            if (lane == 0) out[0] = tt / (float)N;
        }
    }
}

extern "C" void kernel_launch(void* const* d_in, const int* in_sizes, int n_in,
                              void* d_out, int out_size) {
    const float* features = (const float*)d_in[0];
    const void*  labels   = d_in[1];
    (void)in_sizes; (void)n_in; (void)out_size;

    cudaFuncSetAttribute(tile_kernel,
                         cudaFuncAttributeMaxDynamicSharedMemorySize, SMEM_BYTES);

    labels_kernel<<<1, 1024>>>(labels);
    normalize_convert_kernel<<<N, 256>>>(features);
    tile_kernel<<<NTILES, 256, SMEM_BYTES>>>((float*)d_out);
}

// round 9
// speedup vs baseline: 1.2451x; 1.2451x over previous
#include <cuda_runtime.h>
#include <cuda_fp16.h>
#include <math.h>
#include <stdint.h>

#define N 8192
#define D 256
#define K3 256                 // fp16-quantized embedding, exact dist on quantized vecs
#define TM 128
#define TN 128
#define NTB (N / TM)           // 64
#define NTILES (NTB * (NTB + 1) / 2)   // 2080
#define KC 64                  // k-elems per chunk = 128B rows
#define NC (K3 / KC)           // 4
#define MARGIN 0.3f
#define POS_INF_BITS 0x7f800000

// 3-stage smem: stage = A(16KB) + B(16KB)
#define STAGE_BYTES 32768
#define OFF_STAT (3 * STAGE_BYTES)     // 98304
#define STAT_BYTES 4096
#define SMEM_BYTES (OFF_STAT + STAT_BYTES + 1024)

// -------- device scratch --------
__device__ __half g_F[(size_t)N * K3];   // fp16-quantized normalized features
__device__ float g_sq[N];                // exact ||f_hat||^2 in fp32
__device__ int   g_lab[N];
__device__ int   g_maxpos[N];   // d2 float bits (>=0 -> monotone as int); sqrt deferred
__device__ int   g_minneg[N];
__device__ float g_part[8];
__device__ int   g_cnt;

// -------- helpers --------
__device__ __forceinline__ uint32_t smem_u32(const void* p) {
    return (uint32_t)__cvta_generic_to_shared(p);
}
__device__ __forceinline__ uint32_t swz(int row, int g) {   // 128B rows, 16B groups
    return (uint32_t)(row * 128 + ((g ^ (row & 7)) << 4));
}
__device__ __forceinline__ void cp16(uint32_t saddr, const void* gaddr) {
    asm volatile("cp.async.cg.shared.global [%0], [%1], 16;"
                 :: "r"(saddr), "l"(gaddr) : "memory");
}
__device__ __forceinline__ void ldsm4(uint32_t& r0, uint32_t& r1, uint32_t& r2,
                                      uint32_t& r3, uint32_t addr) {
    asm volatile("ldmatrix.sync.aligned.m8n8.x4.shared.b16 {%0,%1,%2,%3}, [%4];"
                 : "=r"(r0), "=r"(r1), "=r"(r2), "=r"(r3) : "r"(addr));
}
__device__ __forceinline__ void mma16816(float* d, const uint32_t* a, const uint32_t* b) {
    asm volatile(
        "mma.sync.aligned.m16n8k16.row.col.f32.f16.f16.f32 "
        "{%0,%1,%2,%3}, {%4,%5,%6,%7}, {%8,%9}, {%0,%1,%2,%3};"
        : "+f"(d[0]), "+f"(d[1]), "+f"(d[2]), "+f"(d[3])
        : "r"(a[0]), "r"(a[1]), "r"(a[2]), "r"(a[3]), "r"(b[0]), "r"(b[1]));
}

// -------- 1) label detect/convert + stats init + counter reset --------
__global__ void labels_kernel(const void* __restrict__ labels_raw) {
    const int* w = (const int*)labels_raw;
    __shared__ int any_odd_nonzero;
    if (threadIdx.x == 0) { any_odd_nonzero = 0; g_cnt = 0; }
    __syncthreads();
    int local = 0;
    for (int i = threadIdx.x; i < N; i += blockDim.x)
        if (w[2 * i + 1] != 0) local = 1;
    if (local) atomicOr(&any_odd_nonzero, 1);
    __syncthreads();
    bool is64 = (any_odd_nonzero == 0);
    for (int i = threadIdx.x; i < N; i += blockDim.x) {
        g_lab[i] = is64 ? w[2 * i] : w[i];
        g_maxpos[i] = 0;
        g_minneg[i] = POS_INF_BITS;
    }
}

// -------- 2) normalize, quantize to fp16, exact sq of quantized --------
__global__ void normalize_convert_kernel(const float* __restrict__ f) {
    int row = blockIdx.x;
    int tid = threadIdx.x;           // 256 = D
    float v = f[row * D + tid];
    float ss = v * v;
    #pragma unroll
    for (int o = 16; o > 0; o >>= 1) ss += __shfl_xor_sync(0xffffffffu, ss, o);
    __shared__ float warp_s[8];
    int wid = tid >> 5, lid = tid & 31;
    if (lid == 0) warp_s[wid] = ss;
    __syncthreads();
    if (wid == 0) {
        float s = (lid < 8) ? warp_s[lid] : 0.0f;
        #pragma unroll
        for (int o = 4; o > 0; o >>= 1) s += __shfl_xor_sync(0xffffffffu, s, o);
        if (lid == 0) warp_s[0] = s;
    }
    __syncthreads();
    float inv = 1.0f / fmaxf(sqrtf(warp_s[0]), 1e-12f);
    __half hq = __float2half_rn(v * inv);
    g_F[(size_t)row * K3 + tid] = hq;
    // second reduction: exact squared norm of the QUANTIZED vector
    float h = __half2float(hq);
    float s2 = h * h;
    #pragma unroll
    for (int o = 16; o > 0; o >>= 1) s2 += __shfl_xor_sync(0xffffffffu, s2, o);
    __syncthreads();
    if (lid == 0) warp_s[wid] = s2;
    __syncthreads();
    if (wid == 0) {
        float s = (lid < 8) ? warp_s[lid] : 0.0f;
        #pragma unroll
        for (int o = 4; o > 0; o >>= 1) s += __shfl_xor_sync(0xffffffffu, s, o);
        if (lid == 0) g_sq[row] = s;
    }
}

// -------- cp.async issue of one k-chunk into one smem stage --------
__device__ __forceinline__ void issue_chunk(uint32_t sb, int gi0, int gj0,
                                            int c, int tid) {
    uint32_t stage = sb + (uint32_t)(c % 3) * STAGE_BYTES;
    #pragma unroll
    for (int l = 0; l < 4; l++) {
        int idx = tid + l * 256;
        int row = idx >> 3, g = idx & 7;
        cp16(stage + swz(row, g),
             g_F + (size_t)(gi0 + row) * K3 + c * KC + g * 8);
        cp16(stage + 16384u + swz(row, g),
             g_F + (size_t)(gj0 + row) * K3 + c * KC + g * 8);
    }
}

// -------- 3) HMMA gram + fused epilogue (d2-space max/min), triangular grid ----
__global__ void __launch_bounds__(256, 2) tile_kernel() {
    // linear index -> (bi, bj) with bj >= bi
    int t = blockIdx.x;
    int p = (int)((sqrtf(8.0f * (float)t + 1.0f) - 1.0f) * 0.5f);
    while ((p + 1) * (p + 2) / 2 <= t) p++;
    while (p * (p + 1) / 2 > t) p--;
    int bi = t - p * (p + 1) / 2;
    int bj = p;

    extern __shared__ __align__(128) char dsm[];
    uint32_t raw = smem_u32(dsm);
    uint32_t sb = (raw + 1023) & ~1023u;
    char* base = dsm + (sb - raw);

    int*   lab_i_s = (int*)(base + OFF_STAT);
    float* sq_i_s  = (float*)(base + OFF_STAT + 512);
    int*   lab_j_s = (int*)(base + OFF_STAT + 1024);
    float* sq_j_s  = (float*)(base + OFF_STAT + 1536);
    int*   smax_i  = (int*)(base + OFF_STAT + 2048);
    int*   smin_i  = (int*)(base + OFF_STAT + 2560);
    int*   smax_j  = (int*)(base + OFF_STAT + 3072);
    int*   smin_j  = (int*)(base + OFF_STAT + 3584);

    int tid = threadIdx.x;
    int wid = tid >> 5, lane = tid & 31;
    int wr = wid & 3, wc = wid >> 2;          // 4x2 warp grid: 32 rows x 64 cols
    int gi0 = bi * TM, gj0 = bj * TN;

    // prologue: chunks 0 and 1 into stages 0,1
    issue_chunk(sb, gi0, gj0, 0, tid);
    asm volatile("cp.async.commit_group;" ::: "memory");
    issue_chunk(sb, gi0, gj0, 1, tid);
    asm volatile("cp.async.commit_group;" ::: "memory");

    if (tid < 128) {
        lab_i_s[tid] = g_lab[gi0 + tid];
        sq_i_s[tid]  = g_sq[gi0 + tid];
        lab_j_s[tid] = g_lab[gj0 + tid];
        sq_j_s[tid]  = g_sq[gj0 + tid];
        smax_i[tid] = 0; smin_i[tid] = POS_INF_BITS;
        smax_j[tid] = 0; smin_j[tid] = POS_INF_BITS;
    }

    float d[16][4];
    #pragma unroll
    for (int q = 0; q < 16; q++)
        #pragma unroll
        for (int r = 0; r < 4; r++) d[q][r] = 0.0f;

    // ldmatrix lane addressing
    int a_row = wr * 32 + ((lane >> 3) & 1) * 8 + (lane & 7);   // + mt*16
    int a_gh  = lane >> 4;
    int b_row = wc * 64 + ((lane >> 4) & 1) * 8 + (lane & 7);   // + p*16
    int b_gh  = (lane >> 3) & 1;

    uint32_t afr[2][8], bfr[2][16];

    for (int c = 0; c < NC; c++) {
        asm volatile("cp.async.wait_group 1;" ::: "memory");
        __syncthreads();
        if (c + 2 < NC) issue_chunk(sb, gi0, gj0, c + 2, tid);
        asm volatile("cp.async.commit_group;" ::: "memory");

        uint32_t abase = sb + (uint32_t)(c % 3) * STAGE_BYTES;
        uint32_t bbase = abase + 16384u;

        // preload kk=0 fragments
        ldsm4(afr[0][0], afr[0][1], afr[0][2], afr[0][3], abase + swz(a_row,      a_gh));
        ldsm4(afr[0][4], afr[0][5], afr[0][6], afr[0][7], abase + swz(a_row + 16, a_gh));
        #pragma unroll
        for (int pp = 0; pp < 4; pp++)
            ldsm4(bfr[0][4 * pp], bfr[0][4 * pp + 1], bfr[0][4 * pp + 2], bfr[0][4 * pp + 3],
                  bbase + swz(b_row + pp * 16, b_gh));

        #pragma unroll
        for (int kk = 0; kk < 4; kk++) {
            int cur = kk & 1, nxt = cur ^ 1;
            if (kk < 3) {   // prefetch kk+1 fragments before consuming kk
                ldsm4(afr[nxt][0], afr[nxt][1], afr[nxt][2], afr[nxt][3],
                      abase + swz(a_row,      (kk + 1) * 2 + a_gh));
                ldsm4(afr[nxt][4], afr[nxt][5], afr[nxt][6], afr[nxt][7],
                      abase + swz(a_row + 16, (kk + 1) * 2 + a_gh));
                #pragma unroll
                for (int pp = 0; pp < 4; pp++)
                    ldsm4(bfr[nxt][4 * pp], bfr[nxt][4 * pp + 1],
                          bfr[nxt][4 * pp + 2], bfr[nxt][4 * pp + 3],
                          bbase + swz(b_row + pp * 16, (kk + 1) * 2 + b_gh));
            }
            #pragma unroll
            for (int mt = 0; mt < 2; mt++)
                #pragma unroll
                for (int nt = 0; nt < 8; nt++)
                    mma16816(d[mt * 8 + nt], &afr[cur][mt * 4], &bfr[cur][nt * 2]);
        }
    }

    // ---- epilogue: masked max/min on d2 (sqrt deferred; monotone) ----
    float rmx[4], rmn[4], si[4];
    int li[4];
    #pragma unroll
    for (int mt = 0; mt < 2; mt++)
        #pragma unroll
        for (int h = 0; h < 2; h++) {
            int row = wr * 32 + mt * 16 + h * 8 + (lane >> 2);
            li[mt * 2 + h] = lab_i_s[row];
            si[mt * 2 + h] = sq_i_s[row];
            rmx[mt * 2 + h] = 0.0f;
            rmn[mt * 2 + h] = __int_as_float(POS_INF_BITS);
        }

    #pragma unroll
    for (int nt = 0; nt < 8; nt++) {
        #pragma unroll
        for (int cc = 0; cc < 2; cc++) {
            int col = wc * 64 + nt * 8 + (lane & 3) * 2 + cc;
            int lj = lab_j_s[col];
            float sj = sq_j_s[col];
            float pmax = 0.0f, nmin = __int_as_float(POS_INF_BITS);
            #pragma unroll
            for (int mt = 0; mt < 2; mt++)
                #pragma unroll
                for (int h = 0; h < 2; h++) {
                    float g = d[mt * 8 + nt][h * 2 + cc];
                    float d2 = fmaxf(si[mt * 2 + h] + sj - 2.0f * g, 1e-12f);
                    if (li[mt * 2 + h] == lj) {
                        rmx[mt * 2 + h] = fmaxf(rmx[mt * 2 + h], d2);
                        pmax = fmaxf(pmax, d2);
                    } else {
                        rmn[mt * 2 + h] = fminf(rmn[mt * 2 + h], d2);
                        nmin = fminf(nmin, d2);
                    }
                }
            unsigned pm = __float_as_uint(pmax), nm = __float_as_uint(nmin);
            #pragma unroll
            for (int o = 4; o <= 16; o <<= 1) {
                unsigned pp = __shfl_xor_sync(0xffffffffu, pm, o);
                unsigned nn = __shfl_xor_sync(0xffffffffu, nm, o);
                pm = pm > pp ? pm : pp;
                nm = nm < nn ? nm : nn;
            }
            if ((lane >> 2) == 0) {
                atomicMax(&smax_j[col], (int)pm);
                atomicMin(&smin_j[col], (int)nm);
            }
        }
    }
    #pragma unroll
    for (int r4 = 0; r4 < 4; r4++) {
        unsigned pm = __float_as_uint(rmx[r4]), nm = __float_as_uint(rmn[r4]);
        #pragma unroll
        for (int o = 1; o <= 2; o <<= 1) {
            unsigned pp = __shfl_xor_sync(0xffffffffu, pm, o);
            unsigned nn = __shfl_xor_sync(0xffffffffu, nm, o);
            pm = pm > pp ? pm : pp;
            nm = nm < nn ? nm : nn;
        }
        if ((lane & 3) == 0) {
            int row = wr * 32 + (r4 >> 1) * 16 + (r4 & 1) * 8 + (lane >> 2);
            atomicMax(&smax_i[row], (int)pm);
            atomicMin(&smin_i[row], (int)nm);
        }
    }
    __syncthreads();
    if (tid < 128) {
        atomicMax(&g_maxpos[gi0 + tid], smax_i[tid]);
        atomicMin(&g_minneg[gi0 + tid], smin_i[tid]);
        atomicMax(&g_maxpos[gj0 + tid], smax_j[tid]);
        atomicMin(&g_minneg[gj0 + tid], smin_j[tid]);
    }
}

// -------- 4) loss: sqrt of hardest d2, relu, mean; 8-block --------
__global__ void loss_kernel(float* __restrict__ out) {
    int b = blockIdx.x, tid = threadIdx.x;   // 8 blocks x 1024 threads
    int i = b * 1024 + tid;
    float mp = sqrtf(__int_as_float(g_maxpos[i]));
    float mn = sqrtf(__int_as_float(g_minneg[i]));
    float l = mp - mn + MARGIN;
    float s = (l > 0.0f) ? l : 0.0f;
    #pragma unroll
    for (int o = 16; o > 0; o >>= 1) s += __shfl_xor_sync(0xffffffffu, s, o);
    __shared__ float warp_s[32];
    int wid = tid >> 5, lid = tid & 31;
    if (lid == 0) warp_s[wid] = s;
    __syncthreads();
    if (wid == 0) {
        float tt = warp_s[lid];
        #pragma unroll
        for (int o = 16; o > 0; o >>= 1) tt += __shfl_xor_sync(0xffffffffu, tt, o);
        if (lid == 0) {
            g_part[b] = tt;
            __threadfence();
            int old = atomicAdd(&g_cnt, 1);
            if (old == 7) {   // last block combines in fixed order -> deterministic
                __threadfence();
                float total = 0.0f;
                volatile float* vp = g_part;
                #pragma unroll
                for (int k = 0; k < 8; k++) total += vp[k];
                out[0] = total / (float)N;
            }
        }
    }
}

extern "C" void kernel_launch(void* const* d_in, const int* in_sizes, int n_in,
                              void* d_out, int out_size) {
    const float* features = (const float*)d_in[0];
    const void*  labels   = d_in[1];
    (void)in_sizes; (void)n_in; (void)out_size;

    cudaFuncSetAttribute(tile_kernel,
                         cudaFuncAttributeMaxDynamicSharedMemorySize, SMEM_BYTES);

    labels_kernel<<<1, 1024>>>(labels);
    normalize_convert_kernel<<<N, 256>>>(features);
    tile_kernel<<<NTILES, 256, SMEM_BYTES>>>();
    loss_kernel<<<8, 1024>>>((float*)d_out);
}